// round 6
// baseline (speedup 1.0000x reference)
#include <cuda_runtime.h>
#include <cuda_bf16.h>
#include <cstdint>

#define IN_F     4096
#define OUT_F    11008
#define MROWS    32
#define GRP      128
#define KSPLIT   2
#define KPER     (IN_F / KSPLIT)          // 2048
#define NGROUPS  (KPER / GRP)             // 16
#define NTILE    32
#define CTAS_COL (OUT_F / NTILE)          // 344
#define THREADS  128

#define XROW_B   272                      // x row: 256B data + 16B pad (odd 16B count -> ldmatrix conflict-free)
#define WROW_W   67                       // w row: 64 words (128 bf16) + 3 pad
#define WROW_B   (WROW_W * 4)             // 268B

__device__ __forceinline__ float bfr(float v) {
    return __bfloat162float(__float2bfloat16(v));
}

__device__ __forceinline__ uint32_t pack_bf16x2(float hi, float lo) {
    uint32_t r;
    asm("cvt.rn.bf16x2.f32 %0, %1, %2;" : "=r"(r) : "f"(hi), "f"(lo));
    return r;
}

__device__ __forceinline__ void hmma(float c[4], const uint32_t a[4],
                                     uint32_t b0, uint32_t b1) {
    asm volatile(
        "mma.sync.aligned.m16n8k16.row.col.f32.bf16.bf16.f32 "
        "{%0,%1,%2,%3}, {%4,%5,%6,%7}, {%8,%9}, {%0,%1,%2,%3};"
        : "+f"(c[0]), "+f"(c[1]), "+f"(c[2]), "+f"(c[3])
        : "r"(a[0]), "r"(a[1]), "r"(a[2]), "r"(a[3]), "r"(b0), "r"(b1));
}

// ---------------------------------------------------------------------------
__global__ void init_out_kernel(const float* __restrict__ bias,
                                float* __restrict__ out)
{
    int o = blockIdx.x * blockDim.x + threadIdx.x;
    if (o < OUT_F) {
        float b = bfr(bias[o]);
        #pragma unroll
        for (int s = 0; s < MROWS; s++)
            out[(size_t)s * OUT_F + o] = b;
    }
}

// ---------------------------------------------------------------------------
// Per CTA: 32 output cols x 2048 K; warp w owns local cols [8w, 8w+8).
// Per group(128 K): stage bf16(x) [32x128] + bf16(qw-qz) [32n x 128k] in SMEM,
// 8 mma.sync k-steps; per-group scale in register epilogue (exact).
// Small tile + low regs -> 4+ CTAs/SM so stage(DRAM) and MMA(LDS) phases of
// different CTAs overlap.
// ---------------------------------------------------------------------------
__global__ void __launch_bounds__(THREADS, 4)
qmain(const float* __restrict__ x, const int* __restrict__ qweight,
      const int* __restrict__ qzeros, const float* __restrict__ scales,
      float* __restrict__ out)
{
    __shared__ __align__(16) uint8_t xs_raw[MROWS * XROW_B];   // 8704 B
    __shared__ __align__(16) uint8_t ws_raw[NTILE * WROW_B];   // 8576 B

    uint32_t xs_b, ws_b;
    asm("{ .reg .u64 t; cvta.to.shared.u64 t, %1; cvt.u32.u64 %0, t; }"
        : "=r"(xs_b) : "l"(xs_raw));
    asm("{ .reg .u64 t; cvta.to.shared.u64 t, %1; cvt.u32.u64 %0, t; }"
        : "=r"(ws_b) : "l"(ws_raw));

    const int tid   = threadIdx.x;
    const int w     = tid >> 5;
    const int l     = tid & 31;
    const int bx    = blockIdx.x;
    const int ctile = bx % CTAS_COL;
    const int kq    = bx / CTAS_COL;
    const int o0    = ctile * NTILE;

    // W conversion mapping: oq = int4-column index (8 per k-row), kpair = k-row pair
    const int oq    = tid & 7;
    const int kpr   = tid >> 3;            // 0..15 -> k rows (2*kpr, 2*kpr+1)
    const int ocol  = 4 * oq;

    // ldmatrix A lane address: row = l&15, k-chunk(8) = l>>4
    const uint32_t a_lane_off = (uint32_t)(l & 15) * XROW_B + (uint32_t)(l >> 4) * 16;

    const int gid = l >> 2;                // fragment group id (row / B-col)
    const int tig = l & 3;                 // thread-in-group

    // accumulators: [m-frag][reg]; per-group temp cg
    float ct[2][4];
    #pragma unroll
    for (int mi = 0; mi < 2; mi++)
        #pragma unroll
        for (int r = 0; r < 4; r++) ct[mi][r] = 0.0f;

    for (int g = 0; g < NGROUPS; g++) {
        const int kb = kq * KPER + g * GRP;
        const int gg = kb >> 7;

        __syncthreads();   // prior group's SMEM reads complete

        // ---- stage x[0:32][kb:kb+128] -> bf16, STS.64 ----
        #pragma unroll
        for (int j = 0; j < 8; j++) {
            int idx = tid + THREADS * j;      // 0..1023
            int s   = idx >> 5;               // row 0..31
            int kq4 = idx & 31;               // float4 index in row
            float4 v = *(const float4*)(x + (size_t)s * IN_F + kb + 4 * kq4);
            uint32_t p0 = pack_bf16x2(v.y, v.x);
            uint32_t p1 = pack_bf16x2(v.w, v.z);
            uint32_t a = xs_b + (uint32_t)s * XROW_B + (uint32_t)kq4 * 8;
            asm volatile("st.shared.v2.b32 [%0], {%1,%2};" :: "r"(a), "r"(p0), "r"(p1));
        }

        // ---- stage W: (qw - qz) -> bf16, transposed to [n][k] ----
        {
            int4 qz = *(const int4*)(qzeros + (size_t)gg * OUT_F + o0 + ocol);
            #pragma unroll
            for (int it = 0; it < 4; it++) {
                int k = 2 * kpr + 32 * it;    // even k-row
                const int* p = qweight + (size_t)(kb + k) * OUT_F + o0 + ocol;
                int4 w0 = *(const int4*)p;
                int4 w1 = *(const int4*)(p + OUT_F);
                uint32_t r0 = pack_bf16x2((float)(w1.x - qz.x), (float)(w0.x - qz.x));
                uint32_t r1 = pack_bf16x2((float)(w1.y - qz.y), (float)(w0.y - qz.y));
                uint32_t r2 = pack_bf16x2((float)(w1.z - qz.z), (float)(w0.z - qz.z));
                uint32_t r3 = pack_bf16x2((float)(w1.w - qz.w), (float)(w0.w - qz.w));
                uint32_t a = ws_b + (uint32_t)ocol * WROW_B + (uint32_t)(k >> 1) * 4;
                asm volatile("st.shared.b32 [%0], %1;" :: "r"(a), "r"(r0));
                asm volatile("st.shared.b32 [%0], %1;" :: "r"(a + WROW_B), "r"(r1));
                asm volatile("st.shared.b32 [%0], %1;" :: "r"(a + 2 * WROW_B), "r"(r2));
                asm volatile("st.shared.b32 [%0], %1;" :: "r"(a + 3 * WROW_B), "r"(r3));
            }
        }

        __syncthreads();

        // ---- 8 k16-steps of mma.sync into per-group accumulators ----
        float cg[2][4];
        #pragma unroll
        for (int mi = 0; mi < 2; mi++)
            #pragma unroll
            for (int r = 0; r < 4; r++) cg[mi][r] = 0.0f;

        #pragma unroll
        for (int ks = 0; ks < 8; ks++) {
            uint32_t a0[4], a1[4];
            uint32_t addr0 = xs_b + a_lane_off + (uint32_t)ks * 32;
            uint32_t addr1 = addr0 + 16u * XROW_B;
            asm volatile("ldmatrix.sync.aligned.m8n8.x4.shared.b16 {%0,%1,%2,%3}, [%4];"
                         : "=r"(a0[0]), "=r"(a0[1]), "=r"(a0[2]), "=r"(a0[3]) : "r"(addr0));
            asm volatile("ldmatrix.sync.aligned.m8n8.x4.shared.b16 {%0,%1,%2,%3}, [%4];"
                         : "=r"(a1[0]), "=r"(a1[1]), "=r"(a1[2]), "=r"(a1[3]) : "r"(addr1));

            uint32_t n = (uint32_t)(w * 8 + gid);   // warp-partitioned N
            uint32_t baddr = ws_b + n * WROW_B + (uint32_t)(ks * 8 + tig) * 4;
            uint32_t b0, b1;
            asm volatile("ld.shared.b32 %0, [%1];" : "=r"(b0) : "r"(baddr));
            asm volatile("ld.shared.b32 %0, [%1];" : "=r"(b1) : "r"(baddr + 16));
            hmma(cg[0], a0, b0, b1);
            hmma(cg[1], a1, b0, b1);
        }

        // ---- per-group scale epilogue (registers only) ----
        {
            float2 scv = *(const float2*)(scales + (size_t)gg * OUT_F
                                          + o0 + w * 8 + 2 * tig);
            float s0 = bfr(scv.x);
            float s1 = bfr(scv.y);
            #pragma unroll
            for (int mi = 0; mi < 2; mi++) {
                ct[mi][0] = fmaf(cg[mi][0], s0, ct[mi][0]);
                ct[mi][1] = fmaf(cg[mi][1], s1, ct[mi][1]);
                ct[mi][2] = fmaf(cg[mi][2], s0, ct[mi][2]);
                ct[mi][3] = fmaf(cg[mi][3], s1, ct[mi][3]);
            }
        }
    }

    // ---- K-split reduction into bias-initialized output ----
    #pragma unroll
    for (int mi = 0; mi < 2; mi++) {
        int s0 = mi * 16 + gid;
        int oc = o0 + w * 8 + 2 * tig;
        atomicAdd(&out[(size_t)s0 * OUT_F + oc],           ct[mi][0]);
        atomicAdd(&out[(size_t)s0 * OUT_F + oc + 1],       ct[mi][1]);
        atomicAdd(&out[(size_t)(s0 + 8) * OUT_F + oc],     ct[mi][2]);
        atomicAdd(&out[(size_t)(s0 + 8) * OUT_F + oc + 1], ct[mi][3]);
    }
}

// ---------------------------------------------------------------------------
// inputs: x f32[1,32,4096], qweight i32[4096,11008], qzeros i32[32,11008],
//         scales f32[32,11008], bias f32[11008]; output f32[1,32,11008]
// ---------------------------------------------------------------------------
extern "C" void kernel_launch(void* const* d_in, const int* in_sizes, int n_in,
                              void* d_out, int out_size)
{
    const float* x       = (const float*)d_in[0];
    const int*   qweight = (const int*)  d_in[1];
    const int*   qzeros  = (const int*)  d_in[2];
    const float* scales  = (const float*)d_in[3];
    const float* bias    = (const float*)d_in[4];
    float*       out     = (float*)d_out;

    init_out_kernel<<<(OUT_F + 255) / 256, 256>>>(bias, out);
    qmain<<<CTAS_COL * KSPLIT, THREADS>>>(x, qweight, qzeros, scales, out);
}